// round 2
// baseline (speedup 1.0000x reference)
#include <cuda_runtime.h>
#include <cuda_bf16.h>
#include <cstdint>

#define NN 256          // NUM_NEURONS
#define NS 512          // NUM_SAMPLES
#define MAXSP 32        // MAX_SPIKES (rounds)
#define NSTEPS 32       // RK4 steps per round
#define V_RESET 1.0f

__device__ __forceinline__ float fast_sigmoid(float v) {
    return 1.0f / (1.0f + __expf(-v));
}

__device__ __forceinline__ void drift(float v, float i, float ic, float mu1, float mu2,
                                      float& dv, float& di, float& ds) {
    dv = mu1 * (i + ic - v);
    di = -mu2 * i;
    ds = fast_sigmoid(v);
}

__device__ __forceinline__ void rk4_step(float v, float i, float s,
                                         float ic, float mu1, float mu2, float h,
                                         float& vn, float& in_, float& sn) {
    float dv1, di1, ds1, dv2, di2, ds2, dv3, di3, ds3, dv4, di4, ds4;
    drift(v, i, ic, mu1, mu2, dv1, di1, ds1);
    float v2 = v + 0.5f * h * dv1;
    float i2 = i + 0.5f * h * di1;
    drift(v2, i2, ic, mu1, mu2, dv2, di2, ds2);
    float v3 = v + 0.5f * h * dv2;
    float i3 = i + 0.5f * h * di2;
    drift(v3, i3, ic, mu1, mu2, dv3, di3, ds3);
    float v4 = v + h * dv3;
    float i4 = i + h * di3;
    drift(v4, i4, ic, mu1, mu2, dv4, di4, ds4);
    float c = h * (1.0f / 6.0f);
    vn  = v + c * (dv1 + 2.0f * dv2 + 2.0f * dv3 + dv4);
    in_ = i + c * (di1 + 2.0f * di2 + 2.0f * di3 + di4);
    sn  = s + c * (ds1 + 2.0f * ds2 + 2.0f * ds3 + ds4);
}

__global__ __launch_bounds__(NN, 4)
void snn_kernel(const float* __restrict__ ic_g,     // [NN]
                const float* __restrict__ w,        // [NN, NN]
                const float* __restrict__ mu_g,     // [2]
                const float* __restrict__ v0_g,     // [NN]
                const float* __restrict__ i0_g,     // [NN]
                const float* __restrict__ s0_g,     // [NS, NN]
                const float* __restrict__ reset_s,  // [MAXSP, NS, NN]
                const int*   __restrict__ t1_p,     // scalar
                float* __restrict__ out_times,      // [NS, MAXSP]
                float* __restrict__ out_vals,       // [NS, MAXSP, NN, 3]
                float* __restrict__ out_marks)      // [NS, MAXSP, NN]
{
    const int smp = blockIdx.x;   // sample
    const int n   = threadIdx.x;  // neuron
    const int warp = n >> 5, lane = n & 31;

    const float t1f = (float)(*t1_p);
    const float mu1 = mu_g[0];
    const float mu2 = mu_g[1];
    const float ic  = ic_g[n];

    float v = v0_g[n];
    float i = i0_g[n];
    float sv = s0_g[smp * NN + n];
    float t0 = 0.0f;

    __shared__ float sprev_sh[NN];
    __shared__ float red_val[8];
    __shared__ int   red_idx[8];
    __shared__ unsigned ballots[8];

    for (int k = 0; k < MAXSP; k++) {
        float dt = (t1f - t0) / (float)NSTEPS;
        bool done = false;
        float tev = t1f;
        float vev, iev, sev;
        bool em = false;

        if (dt > 0.0f) {
            float t = t0;
            #pragma unroll 1
            for (int st = 0; st < NSTEPS; st++) {
                float vn, in_, sn;
                rk4_step(v, i, sv, ic, mu1, mu2, dt, vn, in_, sn);

                // block argmax of sn (tie -> lowest index, matching jnp.argmax)
                sprev_sh[n] = sv;
                float val = sn; int idx = n;
                #pragma unroll
                for (int off = 16; off > 0; off >>= 1) {
                    float ov = __shfl_down_sync(0xffffffffu, val, off);
                    int   oi = __shfl_down_sync(0xffffffffu, idx, off);
                    if (ov > val || (ov == val && oi < idx)) { val = ov; idx = oi; }
                }
                if (lane == 0) { red_val[warp] = val; red_idx[warp] = idx; }
                __syncthreads();
                float mval = red_val[0]; int midx = red_idx[0];
                #pragma unroll
                for (int wv = 1; wv < 8; wv++) {
                    float ov = red_val[wv]; int oi = red_idx[wv];
                    if (ov > mval || (ov == mval && oi < midx)) { mval = ov; midx = oi; }
                }

                if (mval > 0.0f) {
                    // spike triggered this step (uniform across block)
                    float sp = sprev_sh[midx];
                    float snv = mval;
                    float frac = sp / (sp - snv + 1e-12f);
                    frac = fminf(fmaxf(frac, 0.0f), 1.0f);
                    tev = t + frac * dt;
                    vev = v + frac * (vn - v);
                    iev = i + frac * (in_ - i);
                    sev = sv + frac * (sn - sv);
                    em = (sn > 0.0f);
                    v = vev; i = iev; sv = sev;
                    done = true;
                    break;
                } else {
                    v = vn; i = in_; sv = sn;
                    t += dt;
                }
                __syncthreads();  // protect sprev_sh/red_* before next step's writes
            }
        }
        if (!done) { vev = v; iev = i; sev = sv; tev = t1f; }

        // eidx = first neuron with emask set (argmax over bools)
        unsigned b = __ballot_sync(0xffffffffu, em);
        if (lane == 0) ballots[warp] = b;
        __syncthreads();
        int eidx = 0;
        #pragma unroll
        for (int wv = 0; wv < 8; wv++) {
            unsigned bb = ballots[wv];
            if (bb) { eidx = wv * 32 + (__ffs(bb) - 1); break; }
        }

        float wr = done ? w[eidx * NN + n] : 0.0f;
        float rk_s = reset_s[((size_t)k * NS + smp) * NN + n];

        float v_t = vev - (em ? V_RESET : 0.0f);
        float i_t = iev + wr;
        float s_t = fminf(em ? rk_s : sev, 0.0f);

        // write outputs for this round
        size_t base = ((size_t)smp * MAXSP + k) * NN + n;
        if (n == 0) out_times[smp * MAXSP + k] = tev;
        out_vals[base * 3 + 0] = vev;
        out_vals[base * 3 + 1] = iev;
        out_vals[base * 3 + 2] = sev;
        out_marks[base] = em ? 1.0f : 0.0f;

        // carry to next round
        v = v_t; i = i_t; sv = s_t;
        t0 = tev;
        __syncthreads();  // ballots reuse next round
    }
}

extern "C" void kernel_launch(void* const* d_in, const int* in_sizes, int n_in,
                              void* d_out, int out_size) {
    const float* ic      = (const float*)d_in[0];
    const float* w       = (const float*)d_in[1];
    const float* mu      = (const float*)d_in[2];
    const float* v0      = (const float*)d_in[3];
    const float* i0      = (const float*)d_in[4];
    const float* s0      = (const float*)d_in[5];
    const float* reset_s = (const float*)d_in[6];
    const int*   t1      = (const int*)d_in[7];

    float* out = (float*)d_out;
    float* out_times = out;                                    // NS*MAXSP = 16384
    float* out_vals  = out + (size_t)NS * MAXSP;               // NS*MAXSP*NN*3
    float* out_marks = out_vals + (size_t)NS * MAXSP * NN * 3; // NS*MAXSP*NN

    snn_kernel<<<NS, NN>>>(ic, w, mu, v0, i0, s0, reset_s, t1,
                           out_times, out_vals, out_marks);
}